// round 5
// baseline (speedup 1.0000x reference)
#include <cuda_runtime.h>
#include <cstdint>

// Problem dims (fixed by setup_inputs)
#define B_DIM 128
#define T_DIM 100
#define I_DIM 1024
#define O_DIM 1024
#define M_DIM (B_DIM * T_DIM)   // 12800

// ---------------- device scratch (no allocations allowed) ----------------
__device__ float g_h[(size_t)M_DIM * O_DIM];   // h = x @ w   (52.4 MB)
__device__ float g_d[(size_t)O_DIM * O_DIM];   // d = w^T w   (4 MB)
__device__ float g_inv[O_DIM];                 // 1/(norm+eps)
__device__ int   g_cnt[128];                   // per-timestep spike counts

// ---------------- f32x2 packed-FMA helpers (sm_103a) ----------------
__device__ __forceinline__ unsigned long long pack2(float x, float y) {
    unsigned long long r;
    asm("mov.b64 %0, {%1, %2};" : "=l"(r) : "f"(x), "f"(y));
    return r;
}
__device__ __forceinline__ unsigned long long fma2(unsigned long long a,
                                                   unsigned long long b,
                                                   unsigned long long c) {
    unsigned long long d;
    asm("fma.rn.f32x2 %0, %1, %2, %3;" : "=l"(d) : "l"(a), "l"(b), "l"(c));
    return d;
}
__device__ __forceinline__ float2 unpack2(unsigned long long v) {
    float2 f;
    asm("mov.b64 {%0, %1}, %2;" : "=f"(f.x), "=f"(f.y) : "l"(v));
    return f;
}

// ---------------- prep: inv_norm + zero counters ----------------
__global__ void prep_kernel(const float* __restrict__ w) {
    int o = blockIdx.x * blockDim.x + threadIdx.x;
    if (o < O_DIM) {
        float acc = 0.f;
        #pragma unroll 8
        for (int a = 0; a < I_DIM; a++) {
            float t = w[(size_t)a * O_DIM + o];
            acc += t * t;
        }
        g_inv[o] = 1.0f / (acc + 1e-8f);
    }
    if (blockIdx.x == 0 && threadIdx.x < 128) g_cnt[threadIdx.x] = 0;
}

// ---------------- SGEMM NN: g_h = x[12800,1024] @ w[1024,1024] ----------------
// BM=BN=128, BK=8, TM=TN=8, 256 threads, f32x2 packed FMAs.
__global__ __launch_bounds__(256) void sgemm_nn(const float* __restrict__ A,
                                                const float* __restrict__ Bm) {
    __shared__ __align__(16) float As[8][128];
    __shared__ __align__(16) float Bs[8][128];

    const int tid  = threadIdx.x;
    const int K    = I_DIM;
    const int N    = O_DIM;
    const float* Ab = A + (size_t)blockIdx.y * 128 * K;
    const float* Bb = Bm + (size_t)blockIdx.x * 128;
    float* Cb = g_h + (size_t)blockIdx.y * 128 * N + (size_t)blockIdx.x * 128;

    const int aRow = tid >> 1;            // 0..127
    const int aCol = (tid & 1) * 4;       // 0 or 4
    const int bRow = tid >> 5;            // 0..7
    const int bCol = (tid & 31) * 4;      // 0..124

    const int tr = (tid >> 4) * 8;        // thread row base
    const int tc = (tid & 15) * 8;        // thread col base

    unsigned long long acc[8][4];
    #pragma unroll
    for (int i = 0; i < 8; i++)
        #pragma unroll
        for (int j = 0; j < 4; j++) acc[i][j] = 0ull;

    for (int kt = 0; kt < K; kt += 8) {
        float4 av = *(const float4*)(Ab + (size_t)aRow * K + kt + aCol);
        As[aCol + 0][aRow] = av.x;
        As[aCol + 1][aRow] = av.y;
        As[aCol + 2][aRow] = av.z;
        As[aCol + 3][aRow] = av.w;
        float4 bv = *(const float4*)(Bb + (size_t)(kt + bRow) * N + bCol);
        *(float4*)(&Bs[bRow][bCol]) = bv;
        __syncthreads();

        #pragma unroll
        for (int k = 0; k < 8; k++) {
            float rm[8];
            unsigned long long rn[4];
            #pragma unroll
            for (int i = 0; i < 8; i++) rm[i] = As[k][tr + i];
            #pragma unroll
            for (int j = 0; j < 4; j++)
                rn[j] = *reinterpret_cast<const unsigned long long*>(&Bs[k][tc + 2 * j]);
            #pragma unroll
            for (int i = 0; i < 8; i++) {
                unsigned long long am = pack2(rm[i], rm[i]);
                #pragma unroll
                for (int j = 0; j < 4; j++) acc[i][j] = fma2(am, rn[j], acc[i][j]);
            }
        }
        __syncthreads();
    }

    #pragma unroll
    for (int i = 0; i < 8; i++) {
        float o0[8];
        #pragma unroll
        for (int j = 0; j < 4; j++) {
            float2 f = unpack2(acc[i][j]);
            o0[2 * j] = f.x; o0[2 * j + 1] = f.y;
        }
        *(float4*)(Cb + (size_t)(tr + i) * N + tc)     = make_float4(o0[0], o0[1], o0[2], o0[3]);
        *(float4*)(Cb + (size_t)(tr + i) * N + tc + 4) = make_float4(o0[4], o0[5], o0[6], o0[7]);
    }
}

// ---------------- SGEMM TN: g_d = w^T @ w  (1024x1024x1024) ----------------
__global__ __launch_bounds__(256) void sgemm_tn(const float* __restrict__ W) {
    __shared__ __align__(16) float As[8][128];
    __shared__ __align__(16) float Bs[8][128];

    const int tid = threadIdx.x;
    const int N = O_DIM, K = I_DIM;
    const int bRow = tid >> 5;            // 0..7 (k within tile)
    const int bCol = (tid & 31) * 4;      // 0..124

    const int tr = (tid >> 4) * 8;
    const int tc = (tid & 15) * 8;

    unsigned long long acc[8][4];
    #pragma unroll
    for (int i = 0; i < 8; i++)
        #pragma unroll
        for (int j = 0; j < 4; j++) acc[i][j] = 0ull;

    for (int kt = 0; kt < K; kt += 8) {
        // A^T tile: element (m=j, k=a) lives at W[a*N + j] -> natural coalesced load
        float4 av = *(const float4*)(W + (size_t)(kt + bRow) * N + (size_t)blockIdx.y * 128 + bCol);
        *(float4*)(&As[bRow][bCol]) = av;
        float4 bv = *(const float4*)(W + (size_t)(kt + bRow) * N + (size_t)blockIdx.x * 128 + bCol);
        *(float4*)(&Bs[bRow][bCol]) = bv;
        __syncthreads();

        #pragma unroll
        for (int k = 0; k < 8; k++) {
            float rm[8];
            unsigned long long rn[4];
            #pragma unroll
            for (int i = 0; i < 8; i++) rm[i] = As[k][tr + i];
            #pragma unroll
            for (int j = 0; j < 4; j++)
                rn[j] = *reinterpret_cast<const unsigned long long*>(&Bs[k][tc + 2 * j]);
            #pragma unroll
            for (int i = 0; i < 8; i++) {
                unsigned long long am = pack2(rm[i], rm[i]);
                #pragma unroll
                for (int j = 0; j < 4; j++) acc[i][j] = fma2(am, rn[j], acc[i][j]);
            }
        }
        __syncthreads();
    }

    float* Cb = g_d + (size_t)blockIdx.y * 128 * N + (size_t)blockIdx.x * 128;
    #pragma unroll
    for (int i = 0; i < 8; i++) {
        float o0[8];
        #pragma unroll
        for (int j = 0; j < 4; j++) {
            float2 f = unpack2(acc[i][j]);
            o0[2 * j] = f.x; o0[2 * j + 1] = f.y;
        }
        *(float4*)(Cb + (size_t)(tr + i) * N + tc)     = make_float4(o0[0], o0[1], o0[2], o0[3]);
        *(float4*)(Cb + (size_t)(tr + i) * N + tc + 4) = make_float4(o0[4], o0[5], o0[6], o0[7]);
    }
}

// ---------------- scan: one block per batch row, whole T recurrence ----------------
__global__ __launch_bounds__(1024, 1) void scan_kernel(const float* __restrict__ v,
                                                       const float* __restrict__ beta_p,
                                                       const float* __restrict__ b_p,
                                                       float* __restrict__ out) {
    const int b = blockIdx.x;
    const int o = threadIdx.x;
    const int lane = o & 31;
    const int wrp  = o >> 5;

    const float beta   = beta_p[0];
    const float ombeta = 1.0f - beta;
    const float inv    = g_inv[o];
    const float bb     = b_p[o];

    __shared__ int act[1024];         // active spike indices of previous step
    __shared__ unsigned wmask[32];
    __shared__ int wbase[32];

    float mem = 0.0f;
    int k = 0;                        // spk0 = 0

    const float* hrow = g_h + ((size_t)b * T_DIM) * O_DIM + o;
    float* orow = out + ((size_t)b * T_DIM) * O_DIM + o;

    float ht = hrow[0];
    for (int t = 0; t < T_DIM; t++) {
        float htn = (t + 1 < T_DIM) ? hrow[(size_t)(t + 1) * O_DIM] : 0.0f;

        // rst = spk@d row-sums, rec = spk@v row-sums (k is usually 0 or 1)
        float rst = 0.0f, rec = 0.0f;
        for (int i = 0; i < k; i++) {
            int j = act[i];
            rst += g_d[(size_t)j * O_DIM + o];
            rec += v[(size_t)j * O_DIM + o];
        }

        mem = (mem - rst) * beta + (ht + rec) * ombeta;
        float s = (mem * inv - bb) > 0.0f ? 1.0f : 0.0f;
        orow[(size_t)t * O_DIM] = s;

        // deterministic ordered compaction of active indices
        unsigned m = __ballot_sync(0xffffffffu, s != 0.0f);
        if (lane == 0) wmask[wrp] = m;
        __syncthreads();
        if (o < 32) {
            int base = 0;
            for (int w2 = 0; w2 < o; w2++) base += __popc(wmask[w2]);
            wbase[o] = base;
        }
        __syncthreads();
        if (s != 0.0f) {
            int pos = wbase[wrp] + __popc(wmask[wrp] & ((1u << lane) - 1u));
            act[pos] = o;
        }
        k = wbase[31] + __popc(wmask[31]);
        if (o == 0 && k > 0) atomicAdd(&g_cnt[t], k);
        __syncthreads();

        ht = htn;
    }
}

// ---------------- finalize: loss + spread loss ----------------
__global__ void finalize_kernel(float* __restrict__ out) {
    if (threadIdx.x == 0 && blockIdx.x == 0) {
        long long total = 0;
        int mx = 0;
        for (int t = 0; t < T_DIM; t++) {
            int c = g_cnt[t];
            total += c;
            if (c > mx) mx = c;
        }
        out[(size_t)M_DIM * O_DIM]     = 0.5f * (float)total / (float)((long long)B_DIM * T_DIM * O_DIM);
        out[(size_t)M_DIM * O_DIM + 1] = (float)mx / (float)(B_DIM * O_DIM);
    }
}

extern "C" void kernel_launch(void* const* d_in, const int* in_sizes, int n_in,
                              void* d_out, int out_size) {
    const float* x    = (const float*)d_in[0];
    const float* w    = (const float*)d_in[1];
    const float* v    = (const float*)d_in[2];
    const float* beta = (const float*)d_in[3];
    const float* b    = (const float*)d_in[4];
    // d_in[5] = sigma: only used by surrogate gradient (backward), not forward.
    (void)in_sizes; (void)n_in;
    float* out = (float*)d_out;

    prep_kernel<<<4, 256>>>(w);
    sgemm_tn<<<dim3(8, 8), 256>>>(w);
    sgemm_nn<<<dim3(8, 100), 256>>>(x, w);
    scan_kernel<<<128, 1024>>>(v, beta, b, out);
    if (out_size >= (int)((size_t)M_DIM * O_DIM + 2))
        finalize_kernel<<<1, 32>>>(out);
}

// round 7
// speedup vs baseline: 2.2798x; 2.2798x over previous
#include <cuda_runtime.h>
#include <cuda_bf16.h>
#include <cstdint>

// Problem dims (fixed by setup_inputs)
#define B_DIM 128
#define T_DIM 100
#define K_DIM 1024
#define O_DIM 1024
#define M_DIM (B_DIM * T_DIM)   // 12800

// ---------------- device scratch (no allocations allowed) ----------------
__device__ float g_h[(size_t)M_DIM * O_DIM];            // h = x @ w    (52.4 MB)
__device__ float g_d[(size_t)O_DIM * O_DIM];            // d = w^T w    (4 MB)
__device__ __nv_bfloat16 g_xh[(size_t)M_DIM * K_DIM];   // hi(x)        (26.2 MB)
__device__ __nv_bfloat16 g_xl[(size_t)M_DIM * K_DIM];   // lo(x)
__device__ __nv_bfloat16 g_wh[(size_t)O_DIM * K_DIM];   // hi(w^T) K-major (2 MB)
__device__ __nv_bfloat16 g_wl[(size_t)O_DIM * K_DIM];   // lo(w^T)
__device__ float g_inv[O_DIM];                          // 1/(norm+eps)
__device__ int   g_cnt[128];                            // per-timestep spike counts

// ======================= PTX helpers (arch-portable, sm_80+) ==============
__device__ __forceinline__ uint32_t smem_u32(const void* p) {
    uint32_t a;
    asm("{ .reg .u64 t; cvta.to.shared.u64 t, %1; cvt.u32.u64 %0, t; }"
        : "=r"(a) : "l"(p));
    return a;
}

#define CP16(dst, src) \
    asm volatile("cp.async.cg.shared.global [%0], [%1], 16;" \
                 :: "r"(dst), "l"(src) : "memory")
#define CP_COMMIT() asm volatile("cp.async.commit_group;" ::: "memory")
#define CP_WAIT2()  asm volatile("cp.async.wait_group 2;" ::: "memory")

#define LDSM4(r, addr) \
    asm volatile("ldmatrix.sync.aligned.m8n8.x4.shared.b16 {%0,%1,%2,%3}, [%4];" \
                 : "=r"((r)[0]), "=r"((r)[1]), "=r"((r)[2]), "=r"((r)[3]) \
                 : "r"(addr))

#define MMA_BF16(c, a, b0, b1) \
    asm volatile("mma.sync.aligned.m16n8k16.row.col.f32.bf16.bf16.f32 " \
                 "{%0,%1,%2,%3}, {%4,%5,%6,%7}, {%8,%9}, {%0,%1,%2,%3};" \
                 : "+f"((c)[0]), "+f"((c)[1]), "+f"((c)[2]), "+f"((c)[3]) \
                 : "r"((a)[0]), "r"((a)[1]), "r"((a)[2]), "r"((a)[3]), \
                   "r"(b0), "r"(b1))

__device__ __forceinline__ uint32_t pack_bf2(__nv_bfloat16 a, __nv_bfloat16 b) {
    return (uint32_t)__bfloat16_as_ushort(a) |
           ((uint32_t)__bfloat16_as_ushort(b) << 16);
}

// ---------------- prep: inv_norm + zero counters ----------------
__global__ void prep_kernel(const float* __restrict__ w) {
    int o = blockIdx.x * blockDim.x + threadIdx.x;
    if (o < O_DIM) {
        float acc = 0.f;
        #pragma unroll 8
        for (int a = 0; a < K_DIM; a++) {
            float t = w[(size_t)a * O_DIM + o];
            acc += t * t;
        }
        g_inv[o] = 1.0f / (acc + 1e-8f);
    }
    if (blockIdx.x == 0 && threadIdx.x < 128) g_cnt[threadIdx.x] = 0;
}

// ---------------- x -> (xh, xl) bf16 split ----------------
__global__ __launch_bounds__(256) void conv_x(const float* __restrict__ x) {
    size_t i4 = (size_t)blockIdx.x * 256 + threadIdx.x;   // one float4 each
    float4 v = ((const float4*)x)[i4];
    __nv_bfloat16 h0 = __float2bfloat16_rn(v.x);
    __nv_bfloat16 h1 = __float2bfloat16_rn(v.y);
    __nv_bfloat16 h2 = __float2bfloat16_rn(v.z);
    __nv_bfloat16 h3 = __float2bfloat16_rn(v.w);
    __nv_bfloat16 l0 = __float2bfloat16_rn(v.x - __bfloat162float(h0));
    __nv_bfloat16 l1 = __float2bfloat16_rn(v.y - __bfloat162float(h1));
    __nv_bfloat16 l2 = __float2bfloat16_rn(v.z - __bfloat162float(h2));
    __nv_bfloat16 l3 = __float2bfloat16_rn(v.w - __bfloat162float(h3));
    size_t e = i4 * 4;
    *(uint2*)(g_xh + e) = make_uint2(pack_bf2(h0, h1), pack_bf2(h2, h3));
    *(uint2*)(g_xl + e) = make_uint2(pack_bf2(l0, l1), pack_bf2(l2, l3));
}

// ---------------- w[i][o] -> wh/wl[o][i] (transpose + split) ----------------
__global__ __launch_bounds__(256) void conv_w(const float* __restrict__ w) {
    __shared__ float tile[32][33];
    const int tx = threadIdx.x, ty = threadIdx.y;       // (32, 8)
    const int o0 = blockIdx.x * 32, i0 = blockIdx.y * 32;
    #pragma unroll
    for (int j = 0; j < 32; j += 8)
        tile[ty + j][tx] = w[(size_t)(i0 + ty + j) * O_DIM + o0 + tx];  // tile[i][o]
    __syncthreads();
    const int t = ty * 32 + tx;
    const int oo = t >> 3;          // 0..31
    const int c  = (t & 7) * 4;     // i chunk of 4
    __nv_bfloat16 h[4], l[4];
    #pragma unroll
    for (int q = 0; q < 4; q++) {
        float f = tile[c + q][oo];
        h[q] = __float2bfloat16_rn(f);
        l[q] = __float2bfloat16_rn(f - __bfloat162float(h[q]));
    }
    size_t e = (size_t)(o0 + oo) * K_DIM + i0 + c;
    *(uint2*)(g_wh + e) = make_uint2(pack_bf2(h[0], h[1]), pack_bf2(h[2], h[3]));
    *(uint2*)(g_wl + e) = make_uint2(pack_bf2(l[0], l[1]), pack_bf2(l[2], l[3]));
}

// =====================================================================
// bf16x3 TN GEMM via mma.sync: C[m,n] = sum_k A[m,k]*B[n,k]  (K = 1024)
// 3 passes accumulated in registers: Ah*Bh, Ah*Bl, Al*Bh.
// CTA 128x128, BK=64 bf16, 3-stage cp.async pipeline, SW128 swizzle,
// 8 warps (2x4), warp tile 64x32, m16n8k16 bf16 mma.
// =====================================================================
__global__ __launch_bounds__(256) void mma_gemm(
    const __nv_bfloat16* __restrict__ Ah, const __nv_bfloat16* __restrict__ Al,
    const __nv_bfloat16* __restrict__ Bh, const __nv_bfloat16* __restrict__ Bl,
    float* __restrict__ C, int tilesM)
{
    extern __shared__ __align__(128) char dsm[];
    const int tid  = threadIdx.x;
    const int lane = tid & 31;
    const int wid  = tid >> 5;
    const int wm   = wid & 1;        // 2 warps in M
    const int wn   = wid >> 1;       // 4 warps in N

    const int tile = blockIdx.x;
    const int tm = (tile % tilesM) * 128;
    const int tn = (tile / tilesM) * 128;

    const uint32_t sbase = (smem_u32(dsm) + 127u) & ~127u;

    // loader indexing: 128 rows x 8 chunks(16B) per operand tile, 4 rounds
    const int lrow   = tid >> 3;     // 0..31
    const int lchunk = tid & 7;      // 16B chunk within 128B row

    // ldmatrix per-thread base offsets
    const uint32_t xmask = (uint32_t)(lane & 7) << 4;   // SW128 xor
    uint32_t baseA[4], baseB[2];
    #pragma unroll
    for (int mt = 0; mt < 4; mt++) {
        int r = wm * 64 + mt * 16 + (lane & 15);
        baseA[mt] = (uint32_t)(r * 128 + (lane >> 4) * 16);
    }
    #pragma unroll
    for (int nt2 = 0; nt2 < 2; nt2++) {
        int r = wn * 32 + nt2 * 16 + ((lane >> 4) & 1) * 8 + (lane & 7);
        baseB[nt2] = (uint32_t)(r * 128 + ((lane >> 3) & 1) * 16);
    }

    float acc[4][4][4];
    #pragma unroll
    for (int i = 0; i < 4; i++)
        #pragma unroll
        for (int j = 0; j < 4; j++)
            #pragma unroll
            for (int q = 0; q < 4; q++) acc[i][j][q] = 0.f;

    auto load_stage = [&](int j, int stg) {
        const int pass = j >> 4;
        const int kt   = (j & 15) * 64;
        const __nv_bfloat16* Ap = (pass == 2) ? Al : Ah;
        const __nv_bfloat16* Bp = (pass == 1) ? Bl : Bh;
        const uint32_t sA = sbase + (uint32_t)stg * 32768u;
        const uint32_t sB = sA + 16384u;
        #pragma unroll
        for (int i = 0; i < 4; i++) {
            int row = lrow + 32 * i;
            uint32_t off = (uint32_t)(row * 128 + lchunk * 16);
            off ^= (off >> 3) & 0x70u;
            CP16(sA + off, Ap + (size_t)(tm + row) * K_DIM + kt + lchunk * 8);
            CP16(sB + off, Bp + (size_t)(tn + row) * K_DIM + kt + lchunk * 8);
        }
    };

    load_stage(0, 0); CP_COMMIT();
    load_stage(1, 1); CP_COMMIT();

    for (int j = 0; j < 48; j++) {
        if (j + 2 < 48) load_stage(j + 2, (j + 2) % 3);
        CP_COMMIT();
        CP_WAIT2();
        __syncthreads();

        const uint32_t sA = sbase + (uint32_t)(j % 3) * 32768u;
        const uint32_t sB = sA + 16384u;

        #pragma unroll
        for (int kk = 0; kk < 4; kk++) {
            uint32_t a[4][4];
            #pragma unroll
            for (int mt = 0; mt < 4; mt++)
                LDSM4(a[mt], sA + ((baseA[mt] + (uint32_t)kk * 32u) ^ xmask));
            uint32_t b[2][4];
            #pragma unroll
            for (int nt2 = 0; nt2 < 2; nt2++)
                LDSM4(b[nt2], sB + ((baseB[nt2] + (uint32_t)kk * 32u) ^ xmask));
            #pragma unroll
            for (int mt = 0; mt < 4; mt++)
                #pragma unroll
                for (int nt = 0; nt < 4; nt++)
                    MMA_BF16(acc[mt][nt], a[mt],
                             b[nt >> 1][(nt & 1) * 2], b[nt >> 1][(nt & 1) * 2 + 1]);
        }
        __syncthreads();
    }

    // epilogue: direct f32 stores
    #pragma unroll
    for (int mt = 0; mt < 4; mt++) {
        #pragma unroll
        for (int nt = 0; nt < 4; nt++) {
            int row = tm + wm * 64 + mt * 16 + (lane >> 2);
            int col = tn + wn * 32 + nt * 8 + (lane & 3) * 2;
            float* p = C + (size_t)row * O_DIM + col;
            *(float2*)p = make_float2(acc[mt][nt][0], acc[mt][nt][1]);
            *(float2*)(p + 8 * O_DIM) = make_float2(acc[mt][nt][2], acc[mt][nt][3]);
        }
    }
}

// ---------------- scan: one block per batch row, whole T recurrence ----------------
__global__ __launch_bounds__(1024, 1) void scan_kernel(const float* __restrict__ v,
                                                       const float* __restrict__ beta_p,
                                                       const float* __restrict__ b_p,
                                                       float* __restrict__ out) {
    const int b = blockIdx.x;
    const int o = threadIdx.x;
    const int lane = o & 31;
    const int wrp  = o >> 5;

    const float beta   = beta_p[0];
    const float ombeta = 1.0f - beta;
    const float inv    = g_inv[o];
    const float bb     = b_p[o];

    __shared__ int act[1024];
    __shared__ unsigned wmask[32];
    __shared__ int wbase[32];

    float mem = 0.0f;
    int k = 0;

    const float* hrow = g_h + ((size_t)b * T_DIM) * O_DIM + o;
    float* orow = out + ((size_t)b * T_DIM) * O_DIM + o;

    float ht = hrow[0];
    for (int t = 0; t < T_DIM; t++) {
        float htn = (t + 1 < T_DIM) ? hrow[(size_t)(t + 1) * O_DIM] : 0.0f;

        float rst = 0.0f, rec = 0.0f;
        for (int i = 0; i < k; i++) {
            int j = act[i];
            rst += g_d[(size_t)j * O_DIM + o];
            rec += v[(size_t)j * O_DIM + o];
        }

        mem = (mem - rst) * beta + (ht + rec) * ombeta;
        float s = (mem * inv - bb) > 0.0f ? 1.0f : 0.0f;
        orow[(size_t)t * O_DIM] = s;

        unsigned m = __ballot_sync(0xffffffffu, s != 0.0f);
        if (lane == 0) wmask[wrp] = m;
        __syncthreads();
        if (o < 32) {
            int base = 0;
            for (int w2 = 0; w2 < o; w2++) base += __popc(wmask[w2]);
            wbase[o] = base;
        }
        __syncthreads();
        if (s != 0.0f) {
            int pos = wbase[wrp] + __popc(wmask[wrp] & ((1u << lane) - 1u));
            act[pos] = o;
        }
        k = wbase[31] + __popc(wmask[31]);
        if (o == 0 && k > 0) atomicAdd(&g_cnt[t], k);
        __syncthreads();

        ht = htn;
    }
}

// ---------------- finalize: loss + spread loss ----------------
__global__ void finalize_kernel(float* __restrict__ out) {
    if (threadIdx.x == 0 && blockIdx.x == 0) {
        long long total = 0;
        int mx = 0;
        for (int t = 0; t < T_DIM; t++) {
            int c = g_cnt[t];
            total += c;
            if (c > mx) mx = c;
        }
        out[(size_t)M_DIM * O_DIM]     = 0.5f * (float)total / (float)((long long)B_DIM * T_DIM * O_DIM);
        out[(size_t)M_DIM * O_DIM + 1] = (float)mx / (float)(B_DIM * O_DIM);
    }
}

extern "C" void kernel_launch(void* const* d_in, const int* in_sizes, int n_in,
                              void* d_out, int out_size) {
    const float* x    = (const float*)d_in[0];
    const float* w    = (const float*)d_in[1];
    const float* v    = (const float*)d_in[2];
    const float* beta = (const float*)d_in[3];
    const float* b    = (const float*)d_in[4];
    (void)in_sizes; (void)n_in;
    float* out = (float*)d_out;

    const int SMEM_GEMM = 3 * 32768 + 128;   // 98,432 bytes
    cudaFuncSetAttribute((const void*)mma_gemm,
                         cudaFuncAttributeMaxDynamicSharedMemorySize, SMEM_GEMM);

    __nv_bfloat16 *p_xh, *p_xl, *p_wh, *p_wl;
    float *p_h, *p_d;
    cudaGetSymbolAddress((void**)&p_xh, g_xh);
    cudaGetSymbolAddress((void**)&p_xl, g_xl);
    cudaGetSymbolAddress((void**)&p_wh, g_wh);
    cudaGetSymbolAddress((void**)&p_wl, g_wl);
    cudaGetSymbolAddress((void**)&p_h,  g_h);
    cudaGetSymbolAddress((void**)&p_d,  g_d);

    prep_kernel<<<4, 256>>>(w);
    conv_x<<<(M_DIM * K_DIM / 4) / 256, 256>>>(x);                 // 12800 blocks
    conv_w<<<dim3(32, 32), dim3(32, 8)>>>(w);
    // d = w^T w : tiles 8x8 of 128x128
    mma_gemm<<<64, 256, SMEM_GEMM>>>(p_wh, p_wl, p_wh, p_wl, p_d, 8);
    // h = x @ w : tiles 100x8 of 128x128
    mma_gemm<<<800, 256, SMEM_GEMM>>>(p_xh, p_xl, p_wh, p_wl, p_h, 100);
    scan_kernel<<<128, 1024>>>(v, beta, b, out);
    if (out_size >= (int)((size_t)M_DIM * O_DIM + 2))
        finalize_kernel<<<1, 32>>>(out);
}

// round 8
// speedup vs baseline: 2.5772x; 1.1304x over previous
#include <cuda_runtime.h>
#include <cuda_bf16.h>
#include <cstdint>

// Problem dims (fixed by setup_inputs)
#define B_DIM 128
#define T_DIM 100
#define K_DIM 1024
#define O_DIM 1024
#define M_DIM (B_DIM * T_DIM)   // 12800

// ---------------- device scratch (no allocations allowed) ----------------
__device__ float g_h[(size_t)M_DIM * O_DIM];            // h = x @ w    (52.4 MB)
__device__ float g_d[(size_t)O_DIM * O_DIM];            // d = w^T w    (4 MB)
__device__ __nv_bfloat16 g_xh[(size_t)M_DIM * K_DIM];   // hi(x)        (26.2 MB)
__device__ __nv_bfloat16 g_xl[(size_t)M_DIM * K_DIM];   // lo(x)
__device__ __nv_bfloat16 g_wh[(size_t)O_DIM * K_DIM];   // hi(w^T) K-major (2 MB)
__device__ __nv_bfloat16 g_wl[(size_t)O_DIM * K_DIM];   // lo(w^T)
__device__ float g_inv[O_DIM];                          // 1/(norm+eps)
__device__ int   g_cnt[128];                            // per-timestep spike counts

// ======================= PTX helpers (arch-portable, sm_80+) ==============
__device__ __forceinline__ uint32_t smem_u32(const void* p) {
    uint32_t a;
    asm("{ .reg .u64 t; cvta.to.shared.u64 t, %1; cvt.u32.u64 %0, t; }"
        : "=r"(a) : "l"(p));
    return a;
}

#define CP16(dst, src) \
    asm volatile("cp.async.cg.shared.global [%0], [%1], 16;" \
                 :: "r"(dst), "l"(src) : "memory")
#define CP_COMMIT() asm volatile("cp.async.commit_group;" ::: "memory")
#define CP_WAIT2()  asm volatile("cp.async.wait_group 2;" ::: "memory")

#define LDSM4(r, addr) \
    asm volatile("ldmatrix.sync.aligned.m8n8.x4.shared.b16 {%0,%1,%2,%3}, [%4];" \
                 : "=r"((r)[0]), "=r"((r)[1]), "=r"((r)[2]), "=r"((r)[3]) \
                 : "r"(addr))

#define MMA_BF16(c, a, b0, b1) \
    asm volatile("mma.sync.aligned.m16n8k16.row.col.f32.bf16.bf16.f32 " \
                 "{%0,%1,%2,%3}, {%4,%5,%6,%7}, {%8,%9}, {%0,%1,%2,%3};" \
                 : "+f"((c)[0]), "+f"((c)[1]), "+f"((c)[2]), "+f"((c)[3]) \
                 : "r"((a)[0]), "r"((a)[1]), "r"((a)[2]), "r"((a)[3]), \
                   "r"(b0), "r"(b1))

__device__ __forceinline__ uint32_t pack_bf2(__nv_bfloat16 a, __nv_bfloat16 b) {
    return (uint32_t)__bfloat16_as_ushort(a) |
           ((uint32_t)__bfloat16_as_ushort(b) << 16);
}

// ---------------- prep: inv_norm + zero counters ----------------
__global__ void prep_kernel(const float* __restrict__ w) {
    int o = blockIdx.x * blockDim.x + threadIdx.x;
    if (o < O_DIM) {
        float acc = 0.f;
        #pragma unroll 8
        for (int a = 0; a < K_DIM; a++) {
            float t = w[(size_t)a * O_DIM + o];
            acc += t * t;
        }
        g_inv[o] = 1.0f / (acc + 1e-8f);
    }
    if (blockIdx.x == 0 && threadIdx.x < 128) g_cnt[threadIdx.x] = 0;
}

// ---------------- x -> (xh, xl) bf16 split ----------------
__global__ __launch_bounds__(256) void conv_x(const float* __restrict__ x) {
    size_t i4 = (size_t)blockIdx.x * 256 + threadIdx.x;   // one float4 each
    float4 v = ((const float4*)x)[i4];
    __nv_bfloat16 h0 = __float2bfloat16_rn(v.x);
    __nv_bfloat16 h1 = __float2bfloat16_rn(v.y);
    __nv_bfloat16 h2 = __float2bfloat16_rn(v.z);
    __nv_bfloat16 h3 = __float2bfloat16_rn(v.w);
    __nv_bfloat16 l0 = __float2bfloat16_rn(v.x - __bfloat162float(h0));
    __nv_bfloat16 l1 = __float2bfloat16_rn(v.y - __bfloat162float(h1));
    __nv_bfloat16 l2 = __float2bfloat16_rn(v.z - __bfloat162float(h2));
    __nv_bfloat16 l3 = __float2bfloat16_rn(v.w - __bfloat162float(h3));
    size_t e = i4 * 4;
    *(uint2*)(g_xh + e) = make_uint2(pack_bf2(h0, h1), pack_bf2(h2, h3));
    *(uint2*)(g_xl + e) = make_uint2(pack_bf2(l0, l1), pack_bf2(l2, l3));
}

// ---------------- w[i][o] -> wh/wl[o][i] (transpose + split) ----------------
__global__ __launch_bounds__(256) void conv_w(const float* __restrict__ w) {
    __shared__ float tile[32][33];
    const int tx = threadIdx.x, ty = threadIdx.y;       // (32, 8)
    const int o0 = blockIdx.x * 32, i0 = blockIdx.y * 32;
    #pragma unroll
    for (int j = 0; j < 32; j += 8)
        tile[ty + j][tx] = w[(size_t)(i0 + ty + j) * O_DIM + o0 + tx];  // tile[i][o]
    __syncthreads();
    const int t = ty * 32 + tx;
    const int oo = t >> 3;          // 0..31
    const int c  = (t & 7) * 4;     // i chunk of 4
    __nv_bfloat16 h[4], l[4];
    #pragma unroll
    for (int q = 0; q < 4; q++) {
        float f = tile[c + q][oo];
        h[q] = __float2bfloat16_rn(f);
        l[q] = __float2bfloat16_rn(f - __bfloat162float(h[q]));
    }
    size_t e = (size_t)(o0 + oo) * K_DIM + i0 + c;
    *(uint2*)(g_wh + e) = make_uint2(pack_bf2(h[0], h[1]), pack_bf2(h[2], h[3]));
    *(uint2*)(g_wl + e) = make_uint2(pack_bf2(l[0], l[1]), pack_bf2(l[2], l[3]));
}

// =====================================================================
// Fused bf16x3 TN GEMM via mma.sync.
// One grid computes BOTH products:
//   tiles [0, 64)    : d = w^T w   (8x8 tiles of 128x128)
//   tiles [64, 864)  : h = x @ w   (100x8 tiles of 128x128)
// 3 accumulation passes: Ah*Bh, Ah*Bl, Al*Bh.
// CTA 128x128, BK=64 bf16, 3-stage cp.async pipeline, SW128 swizzle,
// 8 warps (2x4), warp tile 64x32, m16n8k16 bf16 mma. 2 CTAs/SM.
// =====================================================================
__global__ __launch_bounds__(256, 2) void mma_gemm_all()
{
    extern __shared__ __align__(128) char dsm[];
    const int tid  = threadIdx.x;
    const int lane = tid & 31;
    const int wid  = tid >> 5;
    const int wm   = wid & 1;        // 2 warps in M
    const int wn   = wid >> 1;       // 4 warps in N

    const __nv_bfloat16 *Ah, *Al, *Bh, *Bl;
    float* C;
    int tm, tn;
    if (blockIdx.x < 64) {
        int t = blockIdx.x;
        tm = (t & 7) * 128; tn = (t >> 3) * 128;
        Ah = g_wh; Al = g_wl; Bh = g_wh; Bl = g_wl; C = g_d;
    } else {
        int t = blockIdx.x - 64;
        tm = (t % 100) * 128; tn = (t / 100) * 128;
        Ah = g_xh; Al = g_xl; Bh = g_wh; Bl = g_wl; C = g_h;
    }

    const uint32_t sbase = (smem_u32(dsm) + 127u) & ~127u;

    // loader indexing: 128 rows x 8 chunks(16B) per operand tile, 4 rounds
    const int lrow   = tid >> 3;     // 0..31
    const int lchunk = tid & 7;      // 16B chunk within 128B row

    // ldmatrix per-thread base offsets
    const uint32_t xmask = (uint32_t)(lane & 7) << 4;   // SW128 xor
    uint32_t baseA[4], baseB[2];
    #pragma unroll
    for (int mt = 0; mt < 4; mt++) {
        int r = wm * 64 + mt * 16 + (lane & 15);
        baseA[mt] = (uint32_t)(r * 128 + (lane >> 4) * 16);
    }
    #pragma unroll
    for (int nt2 = 0; nt2 < 2; nt2++) {
        int r = wn * 32 + nt2 * 16 + ((lane >> 4) & 1) * 8 + (lane & 7);
        baseB[nt2] = (uint32_t)(r * 128 + ((lane >> 3) & 1) * 16);
    }

    float acc[4][4][4];
    #pragma unroll
    for (int i = 0; i < 4; i++)
        #pragma unroll
        for (int j = 0; j < 4; j++)
            #pragma unroll
            for (int q = 0; q < 4; q++) acc[i][j][q] = 0.f;

    auto load_stage = [&](int j, int stg) {
        const int pass = j >> 4;
        const int kt   = (j & 15) * 64;
        const __nv_bfloat16* Ap = (pass == 2) ? Al : Ah;
        const __nv_bfloat16* Bp = (pass == 1) ? Bl : Bh;
        const uint32_t sA = sbase + (uint32_t)stg * 32768u;
        const uint32_t sB = sA + 16384u;
        #pragma unroll
        for (int i = 0; i < 4; i++) {
            int row = lrow + 32 * i;
            uint32_t off = (uint32_t)(row * 128 + lchunk * 16);
            off ^= (off >> 3) & 0x70u;
            CP16(sA + off, Ap + (size_t)(tm + row) * K_DIM + kt + lchunk * 8);
            CP16(sB + off, Bp + (size_t)(tn + row) * K_DIM + kt + lchunk * 8);
        }
    };

    load_stage(0, 0); CP_COMMIT();
    load_stage(1, 1); CP_COMMIT();

    for (int j = 0; j < 48; j++) {
        if (j + 2 < 48) load_stage(j + 2, (j + 2) % 3);
        CP_COMMIT();
        CP_WAIT2();
        __syncthreads();

        const uint32_t sA = sbase + (uint32_t)(j % 3) * 32768u;
        const uint32_t sB = sA + 16384u;

        #pragma unroll
        for (int kk = 0; kk < 4; kk++) {
            uint32_t a[4][4];
            #pragma unroll
            for (int mt = 0; mt < 4; mt++)
                LDSM4(a[mt], sA + ((baseA[mt] + (uint32_t)kk * 32u) ^ xmask));
            uint32_t b[2][4];
            #pragma unroll
            for (int nt2 = 0; nt2 < 2; nt2++)
                LDSM4(b[nt2], sB + ((baseB[nt2] + (uint32_t)kk * 32u) ^ xmask));
            #pragma unroll
            for (int mt = 0; mt < 4; mt++)
                #pragma unroll
                for (int nt = 0; nt < 4; nt++)
                    MMA_BF16(acc[mt][nt], a[mt],
                             b[nt >> 1][(nt & 1) * 2], b[nt >> 1][(nt & 1) * 2 + 1]);
        }
        __syncthreads();
    }

    // epilogue: direct f32 stores
    #pragma unroll
    for (int mt = 0; mt < 4; mt++) {
        #pragma unroll
        for (int nt = 0; nt < 4; nt++) {
            int row = tm + wm * 64 + mt * 16 + (lane >> 2);
            int col = tn + wn * 32 + nt * 8 + (lane & 3) * 2;
            float* p = C + (size_t)row * O_DIM + col;
            *(float2*)p = make_float2(acc[mt][nt][0], acc[mt][nt][1]);
            *(float2*)(p + 8 * O_DIM) = make_float2(acc[mt][nt][2], acc[mt][nt][3]);
        }
    }
}

// ---------------- scan: one block per batch row, whole T recurrence ----------------
__global__ __launch_bounds__(1024, 1) void scan_kernel(const float* __restrict__ v,
                                                       const float* __restrict__ beta_p,
                                                       const float* __restrict__ b_p,
                                                       float* __restrict__ out) {
    const int b = blockIdx.x;
    const int o = threadIdx.x;
    const int lane = o & 31;
    const int wrp  = o >> 5;

    const float beta   = beta_p[0];
    const float ombeta = 1.0f - beta;
    const float inv    = g_inv[o];
    const float bb     = b_p[o];

    __shared__ int act[1024];
    __shared__ unsigned wmask[32];
    __shared__ int wbase[32];
    __shared__ int s_k;

    float mem = 0.0f;
    int k = 0;

    const float* hrow = g_h + ((size_t)b * T_DIM) * O_DIM + o;
    float* orow = out + ((size_t)b * T_DIM) * O_DIM + o;

    float ht = hrow[0];
    for (int t = 0; t < T_DIM; t++) {
        float htn = (t + 1 < T_DIM) ? hrow[(size_t)(t + 1) * O_DIM] : 0.0f;

        float rst = 0.0f, rec = 0.0f;
        for (int i = 0; i < k; i++) {
            int j = act[i];
            rst += g_d[(size_t)j * O_DIM + o];
            rec += v[(size_t)j * O_DIM + o];
        }

        mem = (mem - rst) * beta + (ht + rec) * ombeta;
        float s = (mem * inv - bb) > 0.0f ? 1.0f : 0.0f;
        orow[(size_t)t * O_DIM] = s;

        unsigned m = __ballot_sync(0xffffffffu, s != 0.0f);
        if (lane == 0) wmask[wrp] = m;
        __syncthreads();
        if (o < 32) {
            int c = __popc(wmask[o]);
            int incl = c;
            #pragma unroll
            for (int d2 = 1; d2 < 32; d2 <<= 1) {
                int n = __shfl_up_sync(0xffffffffu, incl, d2);
                if (lane >= d2) incl += n;
            }
            wbase[o] = incl - c;
            if (o == 31) {
                s_k = incl;
                if (incl > 0) atomicAdd(&g_cnt[t], incl);
            }
        }
        __syncthreads();
        if (s != 0.0f) {
            int pos = wbase[wrp] + __popc(wmask[wrp] & ((1u << lane) - 1u));
            act[pos] = o;
        }
        k = s_k;
        __syncthreads();

        ht = htn;
    }
}

// ---------------- finalize: loss + spread loss ----------------
__global__ void finalize_kernel(float* __restrict__ out) {
    if (threadIdx.x == 0 && blockIdx.x == 0) {
        long long total = 0;
        int mx = 0;
        for (int t = 0; t < T_DIM; t++) {
            int c = g_cnt[t];
            total += c;
            if (c > mx) mx = c;
        }
        out[(size_t)M_DIM * O_DIM]     = 0.5f * (float)total / (float)((long long)B_DIM * T_DIM * O_DIM);
        out[(size_t)M_DIM * O_DIM + 1] = (float)mx / (float)(B_DIM * O_DIM);
    }
}

extern "C" void kernel_launch(void* const* d_in, const int* in_sizes, int n_in,
                              void* d_out, int out_size) {
    const float* x    = (const float*)d_in[0];
    const float* w    = (const float*)d_in[1];
    const float* v    = (const float*)d_in[2];
    const float* beta = (const float*)d_in[3];
    const float* b    = (const float*)d_in[4];
    (void)in_sizes; (void)n_in;
    float* out = (float*)d_out;

    const int SMEM_GEMM = 3 * 32768 + 128;   // 98,432 bytes (x2 CTAs = 196.9 KB/SM)
    cudaFuncSetAttribute((const void*)mma_gemm_all,
                         cudaFuncAttributeMaxDynamicSharedMemorySize, SMEM_GEMM);

    prep_kernel<<<4, 256>>>(w);
    conv_x<<<(M_DIM * K_DIM / 4) / 256, 256>>>(x);                 // 12800 blocks
    conv_w<<<dim3(32, 32), dim3(32, 8)>>>(w);
    // fused: 64 d-tiles + 800 h-tiles in one launch
    mma_gemm_all<<<864, 256, SMEM_GEMM>>>();
    scan_kernel<<<128, 1024>>>(v, beta, b, out);
    if (out_size >= (int)((size_t)M_DIM * O_DIM + 2))
        finalize_kernel<<<1, 32>>>(out);
}